// round 7
// baseline (speedup 1.0000x reference)
#include <cuda_runtime.h>
#include <cuda_fp16.h>
#include <cuda_bf16.h>

// ---------------------------------------------------------------------------
// GAT (2-layer, H=4, D=32, IN=128) on GB300, round 6.
//  - separate kernels (mega-kernel proved launch overhead ~0)
//  - f32x2 GEMM + fused el/er epilogue + fp16 feature emit (unchanged)
//  - NEW: edge-parallel weight kernel (exp hoisted out of node loop)
//  - NEW: latency-optimized agg: batch-8 independent gathers, uniform
//    L1 loads for src/weights, redundant per-lane denom, no smem/syncwarp,
//    higher occupancy via __launch_bounds__(256,5)
// ---------------------------------------------------------------------------

#define NN 50000
#define EE 800000
#define FDIM 128
#define NEG_SLOPE 0.2f
#define GTM 64
#define GTK 32

typedef unsigned long long ull;

// -------------------- scratch (static device globals) ----------------------
__device__ __half g_feat_h[NN * FDIM];   // 12.8 MB fp16 features, head-interleaved
__device__ float  g_h1[NN * FDIM];       // 25.6 MB layer-1 output
__device__ int    g_csr_src[EE];         //  3.2 MB
__device__ int    g_csr_dst[EE];         //  3.2 MB
__device__ float4 g_ew[EE];              // 12.8 MB per-edge softmax numerators
__device__ int    g_cnt[NN];
__device__ int    g_row[NN];
__device__ int    g_pos[NN];
__device__ float  g_el[NN * 4];
__device__ float  g_er[NN * 4];
__device__ int    g_bsum[64];

// -------------------- f32x2 helpers -----------------------------------------
__device__ __forceinline__ ull pk2(float lo, float hi) {
    ull r; asm("mov.b64 %0, {%1, %2};" : "=l"(r) : "f"(lo), "f"(hi)); return r;
}
__device__ __forceinline__ void ffma2(ull& d, ull a, ull b) {
    asm("fma.rn.f32x2 %0, %1, %2, %0;" : "+l"(d) : "l"(a), "l"(b));
}
__device__ __forceinline__ float2 unpk(ull v) {
    float2 f; asm("mov.b64 {%0, %1}, %2;" : "=f"(f.x), "=f"(f.y) : "l"(v)); return f;
}

// -------------------- math helpers ------------------------------------------
__device__ __forceinline__ float lrelu(float x) { return x > 0.f ? x : NEG_SLOPE * x; }
__device__ __forceinline__ float elu1(float x)  { return x > 0.f ? x : (__expf(x) - 1.f); }

// -------------------- CSR build --------------------------------------------
__global__ void k_zero_cnt() {
    int i = blockIdx.x * blockDim.x + threadIdx.x;
    if (i < NN) g_cnt[i] = 0;
}

__global__ void k_count(const int* __restrict__ dst) {
    int e = blockIdx.x * blockDim.x + threadIdx.x;
    if (e < EE) atomicAdd(&g_cnt[dst[e]], 1);
}

__global__ void k_scan1() {
    __shared__ int sm[1024];
    int i = blockIdx.x * 1024 + threadIdx.x;
    int v = (i < NN) ? g_cnt[i] : 0;
    sm[threadIdx.x] = v;
    __syncthreads();
#pragma unroll
    for (int off = 1; off < 1024; off <<= 1) {
        int t = (threadIdx.x >= off) ? sm[threadIdx.x - off] : 0;
        __syncthreads();
        sm[threadIdx.x] += t;
        __syncthreads();
    }
    if (i < NN) g_row[i] = sm[threadIdx.x] - v;
    if (threadIdx.x == 1023) g_bsum[blockIdx.x] = sm[1023];
}

__global__ void k_scan2(int nb) {
    int t = threadIdx.x;
    int v = (t < nb) ? g_bsum[t] : 0;
    int lane = t & 31, w = t >> 5;
    int x = v;
#pragma unroll
    for (int off = 1; off < 32; off <<= 1) {
        int y = __shfl_up_sync(0xffffffffu, x, off);
        if (lane >= off) x += y;
    }
    __shared__ int ws[2];
    if (lane == 31) ws[w] = x;
    __syncthreads();
    if (w == 1) x += ws[0];
    if (t < nb) g_bsum[t] = x - v;   // exclusive
}

__global__ void k_scan3() {
    int i = blockIdx.x * blockDim.x + threadIdx.x;
    if (i < NN) {
        int v = g_row[i] + g_bsum[i >> 10];
        g_row[i] = v;
        g_pos[i] = v;
    }
}

__global__ void k_scatter(const int* __restrict__ src, const int* __restrict__ dst) {
    int e = blockIdx.x * blockDim.x + threadIdx.x;
    if (e < EE) {
        int d = dst[e];
        int p = atomicAdd(&g_pos[d], 1);
        g_csr_src[p] = src[e];
        g_csr_dst[p] = d;
    }
}

// -------------------- fused GEMM + el/er + fp16 emit ------------------------
__global__ void __launch_bounds__(256) k_gemm_fused(const float* __restrict__ X,
                                                    const float* __restrict__ W,
                                                    const float* __restrict__ al,
                                                    const float* __restrict__ ar) {
    __shared__ float Xs[GTK][GTM + 2];
    __shared__ float Ws[GTK][FDIM];
    __shared__ __align__(16) __half Hs[GTM][FDIM];

    int t = threadIdx.x;
    int tx = t & 31, ty = t >> 5;
    int row0 = blockIdx.x * GTM;

    ull acc[4][4];
#pragma unroll
    for (int p = 0; p < 4; p++)
#pragma unroll
        for (int c = 0; c < 4; c++) acc[p][c] = 0ull;

    for (int kc = 0; kc < FDIM; kc += GTK) {
#pragma unroll
        for (int i = 0; i < 8; i++) {
            int id = t + i * 256;
            int r = id >> 5, c = id & 31;
            int gr = row0 + r;
            Xs[c][r] = (gr < NN) ? X[gr * FDIM + kc + c] : 0.f;
        }
#pragma unroll
        for (int i = 0; i < 16; i++) {
            int id = t + i * 256;
            int r = id >> 7, c = id & 127;
            Ws[r][c] = W[(kc + r) * FDIM + c];
        }
        __syncthreads();
#pragma unroll
        for (int k = 0; k < GTK; k++) {
            float4 bv = *reinterpret_cast<const float4*>(&Ws[k][tx * 4]);
            ull b0 = pk2(bv.x, bv.x), b1 = pk2(bv.y, bv.y);
            ull b2 = pk2(bv.z, bv.z), b3 = pk2(bv.w, bv.w);
#pragma unroll
            for (int p = 0; p < 4; p++) {
                ull a = *reinterpret_cast<const ull*>(&Xs[k][ty * 8 + p * 2]);
                ffma2(acc[p][0], a, b0);
                ffma2(acc[p][1], a, b1);
                ffma2(acc[p][2], a, b2);
                ffma2(acc[p][3], a, b3);
            }
        }
        __syncthreads();
    }

    float4 alv = *reinterpret_cast<const float4*>(&al[tx * 4]);
    float4 arv = *reinterpret_cast<const float4*>(&ar[tx * 4]);
    int head = tx >> 3;
#pragma unroll
    for (int p = 0; p < 4; p++) {
        float2 v0 = unpk(acc[p][0]);
        float2 v1 = unpk(acc[p][1]);
        float2 v2 = unpk(acc[p][2]);
        float2 v3 = unpk(acc[p][3]);
        int r0 = ty * 8 + p * 2, r1 = r0 + 1;
#pragma unroll
        for (int c = 0; c < 4; c++) {
            int col = tx * 4 + c;
            int pos = ((col & 31) << 2) | (col >> 5);   // head-interleave
            float lo = (c == 0) ? v0.x : (c == 1) ? v1.x : (c == 2) ? v2.x : v3.x;
            float hi = (c == 0) ? v0.y : (c == 1) ? v1.y : (c == 2) ? v2.y : v3.y;
            Hs[r0][pos] = __float2half(lo);
            Hs[r1][pos] = __float2half(hi);
        }
        float pl0 = v0.x * alv.x + v1.x * alv.y + v2.x * alv.z + v3.x * alv.w;
        float pr0 = v0.x * arv.x + v1.x * arv.y + v2.x * arv.z + v3.x * arv.w;
        float pl1 = v0.y * alv.x + v1.y * alv.y + v2.y * alv.z + v3.y * alv.w;
        float pr1 = v0.y * arv.x + v1.y * arv.y + v2.y * arv.z + v3.y * arv.w;
#pragma unroll
        for (int off = 4; off; off >>= 1) {
            pl0 += __shfl_xor_sync(0xffffffffu, pl0, off);
            pr0 += __shfl_xor_sync(0xffffffffu, pr0, off);
            pl1 += __shfl_xor_sync(0xffffffffu, pl1, off);
            pr1 += __shfl_xor_sync(0xffffffffu, pr1, off);
        }
        if ((tx & 7) == 0) {
            if (row0 + r0 < NN) {
                g_el[(row0 + r0) * 4 + head] = pl0;
                g_er[(row0 + r0) * 4 + head] = pr0;
            }
            if (row0 + r1 < NN) {
                g_el[(row0 + r1) * 4 + head] = pl1;
                g_er[(row0 + r1) * 4 + head] = pr1;
            }
        }
    }
    __syncthreads();
#pragma unroll
    for (int i = t; i < GTM * 16; i += 256) {
        int r = i >> 4, c = i & 15;
        int gr = row0 + r;
        if (gr < NN)
            reinterpret_cast<uint4*>(g_feat_h + (size_t)gr * FDIM)[c] =
                reinterpret_cast<const uint4*>(&Hs[r][0])[c];
    }
}

// -------------------- edge-parallel softmax numerators ----------------------
__global__ void __launch_bounds__(256) k_edge_w() {
    int p = blockIdx.x * blockDim.x + threadIdx.x;
    if (p >= EE) return;
    int s = g_csr_src[p];
    int d = g_csr_dst[p];
    float4 l = reinterpret_cast<const float4*>(g_el)[s];
    float4 r = reinterpret_cast<const float4*>(g_er)[d];
    float4 w;
    w.x = __expf(lrelu(l.x + r.x));
    w.y = __expf(lrelu(l.y + r.y));
    w.z = __expf(lrelu(l.z + r.z));
    w.w = __expf(lrelu(l.w + r.w));
    g_ew[p] = w;
}

// -------------------- warp-per-node SpMM (latency-optimized) ----------------
// MODE 1: layer1 -> elu, 128 feats (fp32) to g_h1.  MODE 2: head-mean to out.
template <int MODE>
__global__ void __launch_bounds__(256, 5) k_agg(const float* __restrict__ resid,
                                                const float* __restrict__ bias,
                                                float* __restrict__ out) {
    int node = blockIdx.x * 8 + (threadIdx.x >> 5);
    int lane = threadIdx.x & 31;
    if (node >= NN) return;

    int base = g_row[node];
    int deg  = g_cnt[node];

    float a0 = 0.f, a1 = 0.f, a2 = 0.f, a3 = 0.f;
    float dx = 0.f, dy = 0.f, dz = 0.f, dw = 0.f;

    for (int j0 = 0; j0 < deg; j0 += 8) {
        int s[8];
#pragma unroll
        for (int i = 0; i < 8; i++) {
            int idx = j0 + i;
            idx = (idx < deg) ? idx : (deg - 1);      // clamp (weights zero OOB)
            s[i] = __ldg(&g_csr_src[base + idx]);     // uniform, L1-cached
        }
        uint2 u[8];
#pragma unroll
        for (int i = 0; i < 8; i++)                   // 8 independent gathers
            u[i] = *reinterpret_cast<const uint2*>(g_feat_h + (size_t)s[i] * FDIM + lane * 4);
#pragma unroll
        for (int i = 0; i < 8; i++) {
            float4 w = make_float4(0.f, 0.f, 0.f, 0.f);
            if (j0 + i < deg) w = g_ew[base + j0 + i];  // uniform, L1-cached
            float2 f0 = __half22float2(*reinterpret_cast<__half2*>(&u[i].x));
            float2 f1 = __half22float2(*reinterpret_cast<__half2*>(&u[i].y));
            a0 += w.x * f0.x;  a1 += w.y * f0.y;
            a2 += w.z * f1.x;  a3 += w.w * f1.y;
            dx += w.x; dy += w.y; dz += w.z; dw += w.w;
        }
    }
    // denom identical across lanes — no reduce needed
    float invx = 1.f / fmaxf(dx, 1e-9f);
    float invy = 1.f / fmaxf(dy, 1e-9f);
    float invz = 1.f / fmaxf(dz, 1e-9f);
    float invw = 1.f / fmaxf(dw, 1e-9f);

    float r0 = a0 * invx + resid[node * FDIM + 0  + lane] + bias[0  + lane];
    float r1 = a1 * invy + resid[node * FDIM + 32 + lane] + bias[32 + lane];
    float r2 = a2 * invz + resid[node * FDIM + 64 + lane] + bias[64 + lane];
    float r3 = a3 * invw + resid[node * FDIM + 96 + lane] + bias[96 + lane];

    if (MODE == 1) {
        out[node * FDIM + 0  + lane] = elu1(r0);
        out[node * FDIM + 32 + lane] = elu1(r1);
        out[node * FDIM + 64 + lane] = elu1(r2);
        out[node * FDIM + 96 + lane] = elu1(r3);
    } else {
        out[node * 32 + lane] = 0.25f * (r0 + r1 + r2 + r3);
    }
}

// -------------------- launch ------------------------------------------------
extern "C" void kernel_launch(void* const* d_in, const int* in_sizes, int n_in,
                              void* d_out, int out_size) {
    const float* x   = (const float*)d_in[0];
    const float* W1  = (const float*)d_in[1];
    const float* al1 = (const float*)d_in[2];
    const float* ar1 = (const float*)d_in[3];
    const float* b1  = (const float*)d_in[4];
    const float* W2  = (const float*)d_in[5];
    const float* al2 = (const float*)d_in[6];
    const float* ar2 = (const float*)d_in[7];
    const float* b2  = (const float*)d_in[8];
    const int*   src = (const int*)d_in[9];
    const int*   dst = (const int*)d_in[10];
    float* out = (float*)d_out;

    float* h1 = nullptr;
    cudaGetSymbolAddress((void**)&h1, g_h1);

    const int TB = 256;
    int nblkN = (NN + TB - 1) / TB;
    int nblkE = (EE + TB - 1) / TB;
    int nScan = (NN + 1023) / 1024;          // 49
    int nAgg  = (NN + 7) / 8;                // 6250 (8 warps/block, warp/node)
    int nGemm = (NN + GTM - 1) / GTM;        // 782

    // ---- CSR build (shared by both layers) ----
    k_zero_cnt<<<nblkN, TB>>>();
    k_count<<<nblkE, TB>>>(dst);
    k_scan1<<<nScan, 1024>>>();
    k_scan2<<<1, 64>>>(nScan);
    k_scan3<<<nblkN, TB>>>();
    k_scatter<<<nblkE, TB>>>(src, dst);

    // ---- layer 1 ----
    k_gemm_fused<<<nGemm, 256>>>(x, W1, al1, ar1);
    k_edge_w<<<nblkE, TB>>>();
    k_agg<1><<<nAgg, 256>>>(x, b1, h1);

    // ---- layer 2 ----
    k_gemm_fused<<<nGemm, 256>>>(h1, W2, al2, ar2);
    k_edge_w<<<nblkE, TB>>>();
    k_agg<2><<<nAgg, 256>>>(h1, b2, out);
}